// round 1
// baseline (speedup 1.0000x reference)
#include <cuda_runtime.h>

// Problem constants
#define NB 4096
#define NT 512
#define NC 4
#define NH 32
#define NO 3

// Tiling
#define ROWS 4                 // batch rows per block (1 per half-warp)
#define NTHREADS 64            // 2 warps
#define TCHUNK 16
#define NCHUNK (NT / TCHUNK)   // 32

// Shared layouts (floats). Pads shift banks between rows so the two
// half-warps of a warp (different rows, broadcast within half-warp) hit
// distinct banks.
#define HROW 72                // 64 data (32 dup'd pairs) + 8 pad; 288B, 16B aligned
#define HBUF (ROWS * HROW)     // 288 floats per buffer
#define SROW 132               // 128 data (16 t x 4 dup'd pairs) + 4 pad; 528B

__device__ __forceinline__ unsigned long long pk2(float lo, float hi) {
    unsigned long long d;
    asm("mov.b64 %0, {%1, %2};" : "=l"(d) : "f"(lo), "f"(hi));
    return d;
}
__device__ __forceinline__ void upk2(unsigned long long v, float& lo, float& hi) {
    asm("mov.b64 {%0, %1}, %2;" : "=f"(lo), "=f"(hi) : "l"(v));
}
// Packed dual-FMA: the whole point. SASS should show FFMA2 (2 MACs/issue).
__device__ __forceinline__ unsigned long long fma2(unsigned long long a,
                                                   unsigned long long b,
                                                   unsigned long long c) {
    unsigned long long d;
    asm("fma.rn.f32x2 %0, %1, %2, %3;" : "=l"(d) : "l"(a), "l"(b), "l"(c));
    return d;
}
__device__ __forceinline__ unsigned long long add2(unsigned long long a,
                                                   unsigned long long b) {
    unsigned long long d;
    asm("add.rn.f32x2 %0, %1, %2;" : "=l"(d) : "l"(a), "l"(b));
    return d;
}
__device__ __forceinline__ void lds_2x64(unsigned addr, unsigned long long& a,
                                         unsigned long long& b) {
    asm volatile("ld.shared.v2.u64 {%0, %1}, [%2];" : "=l"(a), "=l"(b) : "r"(addr));
}
__device__ __forceinline__ void sts_v4(unsigned addr, float a, float b, float c, float d) {
    asm volatile("st.shared.v4.b32 [%0], {%1, %2, %3, %4};"
                 :: "r"(addr), "f"(a), "f"(b), "f"(c), "f"(d) : "memory");
}
__device__ __forceinline__ float lds_f32(unsigned addr) {
    float v;
    asm volatile("ld.shared.f32 %0, [%1];" : "=f"(v) : "r"(addr));
    return v;
}

__global__ void __launch_bounds__(NTHREADS, 7)
rnn_fused_kernel(const float* __restrict__ seq,
                 const float* __restrict__ w_ih,
                 const float* __restrict__ w_hh,
                 const float* __restrict__ b_ih,
                 const float* __restrict__ b_hh,
                 const float* __restrict__ fc_w,
                 const float* __restrict__ fc_b,
                 float* __restrict__ out) {
    __shared__ float hs[2 * HBUF];       // double-buffered dup'd hidden state
    __shared__ float ss[ROWS * SROW];    // dup'd seq chunk

    const int tid   = threadIdx.x;
    const int lane  = tid & 31;
    const int warp  = tid >> 5;
    const int half  = lane >> 4;
    const int g     = lane & 15;         // lane within half-warp: owns hidden 2g, 2g+1
    const int row_l = warp * 2 + half;   // row within block
    const int row   = blockIdx.x * ROWS + row_l;
    const int j0 = 2 * g, j1 = 2 * g + 1;

    // ---- one-time weight load into registers (packed pairs) ----
    unsigned long long w2[NH];
#pragma unroll
    for (int k = 0; k < NH; k++)
        w2[k] = pk2(w_hh[j0 * NH + k], w_hh[j1 * NH + k]);

    unsigned long long wi2[NC];
#pragma unroll
    for (int c = 0; c < NC; c++)
        wi2[c] = pk2(w_ih[j0 * NC + c], w_ih[j1 * NC + c]);

    const unsigned long long bias2 = pk2(b_ih[j0] + b_hh[j0], b_ih[j1] + b_hh[j1]);

    // ---- shared addresses ----
    const unsigned hbase = (unsigned)__cvta_generic_to_shared(hs);
    const unsigned sbase = (unsigned)__cvta_generic_to_shared(ss);
    const unsigned hrow0 = hbase + row_l * (HROW * 4);        // buffer 0, this row
    const unsigned hwr0  = hrow0 + g * 16;                    // write slot (pair j0,j1)
    const unsigned srow  = sbase + row_l * (SROW * 4);

    // h(t=0) = 0 in buffer 0 (the first read buffer)
    sts_v4(hwr0, 0.f, 0.f, 0.f, 0.f);

    const float* seqp = seq + (size_t)row * (NT * NC);

    // prefetch seq chunk 0 (lane g -> timestep g of chunk)
    float4 nxt = *(const float4*)(seqp + g * NC);

    __syncwarp();

    for (int ch = 0; ch < NCHUNK; ch++) {
        // stage seq chunk as duplicated pairs: [sx,sx,sy,sy,sz,sz,sw,sw]
        sts_v4(srow + g * 32,      nxt.x, nxt.x, nxt.y, nxt.y);
        sts_v4(srow + g * 32 + 16, nxt.z, nxt.z, nxt.w, nxt.w);
        __syncwarp();
        if (ch + 1 < NCHUNK)
            nxt = *(const float4*)(seqp + ((ch + 1) * TCHUNK + g) * NC);

#pragma unroll
        for (int tt = 0; tt < TCHUNK; tt++) {
            const int par = tt & 1;  // global parity: TCHUNK is even
            const unsigned rd = hrow0 + par * (HBUF * 4);          // read  buf[par]
            const unsigned wr = hwr0  + (par ^ 1) * (HBUF * 4);    // write buf[par^1]

            // x_proj for this (row, t): dup'd seq pairs from shared
            unsigned long long sa, sb, sc, sd;
            lds_2x64(srow + tt * 32,      sa, sb);
            lds_2x64(srow + tt * 32 + 16, sc, sd);
            unsigned long long acc0 = fma2(wi2[0], sa, bias2);
            unsigned long long acc1 = fma2(wi2[1], sb, 0ULL);
            acc0 = fma2(wi2[2], sc, acc0);
            acc1 = fma2(wi2[3], sd, acc1);

            // recurrence: 32 packed MACs, two accumulator chains
#pragma unroll
            for (int k = 0; k < NH; k += 2) {
                unsigned long long h0, h1;
                lds_2x64(rd + k * 8, h0, h1);  // (h_k,h_k), (h_{k+1},h_{k+1})
                acc0 = fma2(w2[k],     h0, acc0);
                acc1 = fma2(w2[k + 1], h1, acc1);
            }
            const unsigned long long acc = add2(acc0, acc1);

            float a0, a1;
            upk2(acc, a0, a1);
            a0 = fmaxf(a0, 0.0f);
            a1 = fmaxf(a1, 0.0f);

            // publish new h pair (duplicated) to the other buffer
            sts_v4(wr, a0, a0, a1, a1);
            __syncwarp();  // orders: this step's writes < next step's reads,
                           // and (transitively) prev step's reads < this step's writes
        }
    }

    // ---- FC head: final h is in buffer 0 (t=511 wrote par^1 = 0) ----
    if (g < NO) {
        float acc = fc_b[g];
        const unsigned rd = hrow0;  // buffer 0
#pragma unroll
        for (int k = 0; k < NH; k++)
            acc = fmaf(lds_f32(rd + k * 8), fc_w[g * NH + k], acc);
        out[row * NO + g] = acc;
    }
}

extern "C" void kernel_launch(void* const* d_in, const int* in_sizes, int n_in,
                              void* d_out, int out_size) {
    const float* seq  = (const float*)d_in[0];
    const float* w_ih = (const float*)d_in[1];
    const float* w_hh = (const float*)d_in[2];
    const float* b_ih = (const float*)d_in[3];
    const float* b_hh = (const float*)d_in[4];
    const float* fc_w = (const float*)d_in[5];
    const float* fc_b = (const float*)d_in[6];
    float* out = (float*)d_out;

    rnn_fused_kernel<<<NB / ROWS, NTHREADS>>>(seq, w_ih, w_hh, b_ih, b_hh,
                                              fc_w, fc_b, out);
}

// round 2
// speedup vs baseline: 1.1201x; 1.1201x over previous
#include <cuda_runtime.h>

// Problem constants
#define NB 4096
#define NT 512
#define NC 4
#define NH 32
#define NO 3

// Tiling
#define ROWS 4                 // batch rows per block (1 per half-warp)
#define NTHREADS 64            // 2 warps
#define TCHUNK 16
#define NCHUNK (NT / TCHUNK)   // 32

// Shared layouts (floats), padded so the 4 rows land in distinct banks.
#define HROW 36                // 32 h values + 4 pad; 144 B (16B aligned)
#define HBUF (ROWS * HROW)     // one buffer = 144 floats (576 B)
#define SROW 68                // 16 t x 4 floats + 4 pad; 272 B (16B aligned)

__device__ __forceinline__ unsigned long long pk2(float lo, float hi) {
    unsigned long long d;
    asm("mov.b64 %0, {%1, %2};" : "=l"(d) : "f"(lo), "f"(hi));
    return d;
}
__device__ __forceinline__ void upk2(unsigned long long v, float& lo, float& hi) {
    asm("mov.b64 {%0, %1}, %2;" : "=f"(lo), "=f"(hi) : "l"(v));
}
// Packed dual-FMA (FFMA2 in SASS): 2 MACs per issue.
__device__ __forceinline__ unsigned long long fma2(unsigned long long a,
                                                   unsigned long long b,
                                                   unsigned long long c) {
    unsigned long long d;
    asm("fma.rn.f32x2 %0, %1, %2, %3;" : "=l"(d) : "l"(a), "l"(b), "l"(c));
    return d;
}
__device__ __forceinline__ unsigned long long add2(unsigned long long a,
                                                   unsigned long long b) {
    unsigned long long d;
    asm("add.rn.f32x2 %0, %1, %2;" : "=l"(d) : "l"(a), "l"(b));
    return d;
}
__device__ __forceinline__ void lds_2x64(unsigned addr, unsigned long long& a,
                                         unsigned long long& b) {
    asm volatile("ld.shared.v2.u64 {%0, %1}, [%2];" : "=l"(a), "=l"(b) : "r"(addr));
}
__device__ __forceinline__ void sts_64(unsigned addr, unsigned long long v) {
    asm volatile("st.shared.u64 [%0], %1;" :: "r"(addr), "l"(v) : "memory");
}
__device__ __forceinline__ void sts_v4(unsigned addr, float a, float b, float c, float d) {
    asm volatile("st.shared.v4.b32 [%0], {%1, %2, %3, %4};"
                 :: "r"(addr), "f"(a), "f"(b), "f"(c), "f"(d) : "memory");
}
__device__ __forceinline__ float lds_f32(unsigned addr) {
    float v;
    asm volatile("ld.shared.f32 %0, [%1];" : "=f"(v) : "r"(addr));
    return v;
}

__global__ void __launch_bounds__(NTHREADS, 9)
rnn_fused_kernel(const float* __restrict__ seq,
                 const float* __restrict__ w_ih,
                 const float* __restrict__ w_hh,
                 const float* __restrict__ b_ih,
                 const float* __restrict__ b_hh,
                 const float* __restrict__ fc_w,
                 const float* __restrict__ fc_b,
                 float* __restrict__ out) {
    __shared__ float hs[2 * HBUF];       // double-buffered hidden state (plain layout)
    __shared__ float ss[ROWS * SROW];    // seq chunk (plain layout)

    const int tid   = threadIdx.x;
    const int lane  = tid & 31;
    const int warp  = tid >> 5;
    const int half  = lane >> 4;
    const int g     = lane & 15;         // lane within half-warp: owns hidden 2g, 2g+1
    const int row_l = warp * 2 + half;   // row within block
    const int row   = blockIdx.x * ROWS + row_l;
    const int j0 = 2 * g, j1 = 2 * g + 1;

    // ---- one-time weight load into registers, packed along k (pairs k,k+1) ----
    unsigned long long wA[NH / 2], wB[NH / 2];
#pragma unroll
    for (int p = 0; p < NH / 2; p++) {
        wA[p] = pk2(w_hh[j0 * NH + 2 * p], w_hh[j0 * NH + 2 * p + 1]);
        wB[p] = pk2(w_hh[j1 * NH + 2 * p], w_hh[j1 * NH + 2 * p + 1]);
    }
    const unsigned long long wiA0 = pk2(w_ih[j0 * NC + 0], w_ih[j0 * NC + 1]);
    const unsigned long long wiA1 = pk2(w_ih[j0 * NC + 2], w_ih[j0 * NC + 3]);
    const unsigned long long wiB0 = pk2(w_ih[j1 * NC + 0], w_ih[j1 * NC + 1]);
    const unsigned long long wiB1 = pk2(w_ih[j1 * NC + 2], w_ih[j1 * NC + 3]);

    // bias folded as (bias, 0): the end-of-step horizontal add counts it once
    const unsigned long long biasA = pk2(b_ih[j0] + b_hh[j0], 0.0f);
    const unsigned long long biasB = pk2(b_ih[j1] + b_hh[j1], 0.0f);

    // ---- shared addresses ----
    const unsigned hbase = (unsigned)__cvta_generic_to_shared(hs);
    const unsigned sbase = (unsigned)__cvta_generic_to_shared(ss);
    const unsigned hrow0 = hbase + row_l * (HROW * 4);   // buffer 0, this row
    const unsigned hwr0  = hrow0 + g * 8;                // this lane's h pair slot
    const unsigned srow  = sbase + row_l * (SROW * 4);

    // h(t=0) = 0 in buffer 0 (the first read buffer)
    sts_64(hwr0, 0ULL);

    const float* seqp = seq + (size_t)row * (NT * NC);

    // prefetch seq chunk 0 (lane g -> timestep g of chunk)
    float4 nxt = *(const float4*)(seqp + g * NC);

    __syncwarp();

    for (int ch = 0; ch < NCHUNK; ch++) {
        // stage seq chunk plainly: 16 B per timestep
        sts_v4(srow + g * 16, nxt.x, nxt.y, nxt.z, nxt.w);
        __syncwarp();
        if (ch + 1 < NCHUNK)
            nxt = *(const float4*)(seqp + ((ch + 1) * TCHUNK + g) * NC);

#pragma unroll
        for (int tt = 0; tt < TCHUNK; tt++) {
            const int par = tt & 1;  // global step parity (TCHUNK even)
            const unsigned rd = hrow0 + par * (HBUF * 4);          // read  buf[par]
            const unsigned wr = hwr0  + (par ^ 1) * (HBUF * 4);    // write buf[par^1]

            // x_proj: seq pairs (s0,s1),(s2,s3) from shared
            unsigned long long sa, sb;
            lds_2x64(srow + tt * 16, sa, sb);
            unsigned long long accA0 = fma2(sa, wiA0, biasA);
            unsigned long long accB0 = fma2(sa, wiB0, biasB);
            unsigned long long accA1 = fma2(sb, wiA1, 0ULL);
            unsigned long long accB1 = fma2(sb, wiB1, 0ULL);

            // recurrence: 8 LDS fetch all 32 h as 16 packed (h_2p, h_2p+1) pairs
#pragma unroll
            for (int p = 0; p < NH / 2; p += 2) {
                unsigned long long h0, h1;
                lds_2x64(rd + p * 8, h0, h1);
                accA0 = fma2(wA[p],     h0, accA0);
                accB0 = fma2(wB[p],     h0, accB0);
                accA1 = fma2(wA[p + 1], h1, accA1);
                accB1 = fma2(wB[p + 1], h1, accB1);
            }

            // horizontal reduce + relu
            float aLo, aHi, bLo, bHi;
            upk2(add2(accA0, accA1), aLo, aHi);
            upk2(add2(accB0, accB1), bLo, bHi);
            const float a = fmaxf(aLo + aHi, 0.0f);
            const float b = fmaxf(bLo + bHi, 0.0f);

            // publish new h pair to the other buffer
            sts_64(wr, pk2(a, b));
            __syncwarp();  // orders this step's writes < next step's reads
        }
    }

    // ---- FC head: final h is in buffer 0 (step 511 has par=1, writes buf 0) ----
    if (g < NO) {
        float acc = fc_b[g];
        const unsigned rd = hrow0;  // buffer 0
#pragma unroll
        for (int k = 0; k < NH; k++)
            acc = fmaf(lds_f32(rd + k * 4), fc_w[g * NH + k], acc);
        out[row * NO + g] = acc;
    }
}

extern "C" void kernel_launch(void* const* d_in, const int* in_sizes, int n_in,
                              void* d_out, int out_size) {
    const float* seq  = (const float*)d_in[0];
    const float* w_ih = (const float*)d_in[1];
    const float* w_hh = (const float*)d_in[2];
    const float* b_ih = (const float*)d_in[3];
    const float* b_hh = (const float*)d_in[4];
    const float* fc_w = (const float*)d_in[5];
    const float* fc_b = (const float*)d_in[6];
    float* out = (float*)d_out;

    rnn_fused_kernel<<<NB / ROWS, NTHREADS>>>(seq, w_ih, w_hh, b_ih, b_hh,
                                              fc_w, fc_b, out);
}